// round 8
// baseline (speedup 1.0000x reference)
#include <cuda_runtime.h>
#include <math.h>

#define BB 4
#define CC 64
#define LL 16384
#define BL 65536
#define DI 128
#define DS 16
#define NKF 65
#define NIMG 256
#define NCHK 64
#define CHKS 256
#define FPIX (NKF*128)   // 8320 freq pixels per image

__device__ float d_xz [BL*256];
__device__ float d_xc [BL*DI];
__device__ float d_dbc[BL*36];
__device__ float d_dt [BL*DI];
__device__ float d_hloc[BB*DI*NCHK*DS];
__device__ float d_cd  [BB*DI*NCHK];
__device__ float d_Hst [BB*DI*NCHK*DS];
__device__ float d_ygt [BB*DI*LL];
__device__ float d_xsp [BB*CC*LL];
__device__ float d_RT  [32768*130];
__device__ float d_Cre [NIMG*FPIX];
__device__ float d_Cim [NIMG*FPIX];
__device__ float d_mag [NIMG*FPIX];
__device__ float d_M1  [NIMG*FPIX];
__device__ float d_M2  [NIMG*FPIX];
__device__ float d_Zr  [NIMG*FPIX];
__device__ float d_Zi  [NIMG*FPIX];
__device__ float d_Yr  [NIMG*FPIX];
__device__ float d_Yi  [NIMG*FPIX];
__device__ float d_xfr [BB*CC*LL];
__device__ float d_TW1 [128*130];
__device__ float d_TCOS[128*128];
__device__ float d_TSIN[128*128];
__device__ float d_TSINN[128*128];
__device__ float d_IRW1[NKF*128];
__device__ float d_IRW2[NKF*128];

__global__ void gen_tables() {
    int i = blockIdx.x*256 + threadIdx.x;
    if (i < 128*130) {
        int w = i/130, j = i%130;
        int k = (j < NKF) ? j : j-NKF;
        float s,c; sincospif((float)((w*k)&127)/64.0f, &s, &c);
        d_TW1[i] = (j < NKF) ? c : -s;
    }
    if (i < 128*128) {
        int u = i/128, h = i%128;
        float s,c; sincospif((float)((u*h)&127)/64.0f, &s, &c);
        d_TCOS[i]=c; d_TSIN[i]=s; d_TSINN[i]=-s;
    }
    if (i < NKF*128) {
        int kf = i/128, w = i%128;
        float a = (kf==0 || kf==64) ? 1.0f : 2.0f;
        float s,c; sincospif((float)((kf*w)&127)/64.0f, &s, &c);
        d_IRW1[i] =  a*c*(1.0f/16384.0f);
        d_IRW2[i] = -a*s*(1.0f/16384.0f);
    }
}

// C[m,n] = sum_k A[m,k]*B[k,n] (+ A2[m,k]*B2[k,n] if DUAL)
template<bool DUAL>
__global__ void sgemm(const float* __restrict__ A, const float* __restrict__ A2,
                      int lda_m, int lda_k, int sA,
                      const float* __restrict__ B, const float* __restrict__ B2,
                      int ldb_k, int ldb_n, int sB,
                      float* __restrict__ C, int ldc, int sC,
                      int M, int N, int K,
                      const float* __restrict__ bias, int biasMode, int doRelu)
{
    __shared__ float As[16][68], Bs[16][68], As2[16][68], Bs2[16][68];
    int bz = blockIdx.z;
    const float* Ab  = A + (size_t)bz*sA;
    const float* Bb  = B + (size_t)bz*sB;
    const float* A2b = DUAL ? (A2 + (size_t)bz*sA) : A;
    const float* B2b = DUAL ? (B2 + (size_t)bz*sB) : B;
    float* Cb = C + (size_t)bz*sC;
    int m0 = blockIdx.y<<6, n0 = blockIdx.x<<6;
    int tid = threadIdx.x, tx = tid&15, ty = tid>>4;
    float acc[4][4];
#pragma unroll
    for (int i=0;i<4;i++)
#pragma unroll
        for (int j=0;j<4;j++) acc[i][j]=0.f;

    for (int k0 = 0; k0 < K; k0 += 16) {
        if (lda_k == 1) {
            int kl = tid&15, ml0 = tid>>4;
#pragma unroll
            for (int i=0;i<4;i++) {
                int ml = ml0 + (i<<4), m = m0+ml, k = k0+kl;
                bool ok = (m<M)&&(k<K);
                As[kl][ml] = ok ? Ab[(size_t)m*lda_m + k] : 0.f;
                if (DUAL) As2[kl][ml] = ok ? A2b[(size_t)m*lda_m + k] : 0.f;
            }
        } else {
            int ml = tid&63, kl0 = tid>>6;
#pragma unroll
            for (int i=0;i<4;i++) {
                int kl = kl0 + (i<<2), m = m0+ml, k = k0+kl;
                bool ok = (m<M)&&(k<K);
                As[kl][ml] = ok ? Ab[(size_t)m*lda_m + (size_t)k*lda_k] : 0.f;
                if (DUAL) As2[kl][ml] = ok ? A2b[(size_t)m*lda_m + (size_t)k*lda_k] : 0.f;
            }
        }
        if (ldb_n == 1) {
            int nl = tid&63, kl0 = tid>>6;
#pragma unroll
            for (int i=0;i<4;i++) {
                int kl = kl0 + (i<<2), n = n0+nl, k = k0+kl;
                bool ok = (k<K)&&(n<N);
                Bs[kl][nl] = ok ? Bb[(size_t)k*ldb_k + n] : 0.f;
                if (DUAL) Bs2[kl][nl] = ok ? B2b[(size_t)k*ldb_k + n] : 0.f;
            }
        } else {
            int kl = tid&15, nl0 = tid>>4;
#pragma unroll
            for (int i=0;i<4;i++) {
                int nl = nl0 + (i<<4), n = n0+nl, k = k0+kl;
                bool ok = (k<K)&&(n<N);
                Bs[kl][nl] = ok ? Bb[(size_t)k*ldb_k + (size_t)n*ldb_n] : 0.f;
                if (DUAL) Bs2[kl][nl] = ok ? B2b[(size_t)k*ldb_k + (size_t)n*ldb_n] : 0.f;
            }
        }
        __syncthreads();
#pragma unroll
        for (int kk=0; kk<16; kk++) {
            float4 av = *(const float4*)&As[kk][ty<<2];
            float4 bv = *(const float4*)&Bs[kk][tx<<2];
            float a[4]={av.x,av.y,av.z,av.w}, b[4]={bv.x,bv.y,bv.z,bv.w};
#pragma unroll
            for (int i=0;i<4;i++)
#pragma unroll
                for (int j=0;j<4;j++) acc[i][j] = fmaf(a[i], b[j], acc[i][j]);
            if (DUAL) {
                float4 av2 = *(const float4*)&As2[kk][ty<<2];
                float4 bv2 = *(const float4*)&Bs2[kk][tx<<2];
                float a2[4]={av2.x,av2.y,av2.z,av2.w}, b2[4]={bv2.x,bv2.y,bv2.z,bv2.w};
#pragma unroll
                for (int i=0;i<4;i++)
#pragma unroll
                    for (int j=0;j<4;j++) acc[i][j] = fmaf(a2[i], b2[j], acc[i][j]);
            }
        }
        __syncthreads();
    }
#pragma unroll
    for (int i=0;i<4;i++) {
        int m = m0 + (ty<<2) + i;
        if (m >= M) continue;
#pragma unroll
        for (int j=0;j<4;j++) {
            int n = n0 + (tx<<2) + j;
            if (n >= N) continue;
            float v = acc[i][j];
            if (biasMode == 1) v += bias[n];
            else if (biasMode == 2) v += bias[m];
            if (doRelu) v = fmaxf(v, 0.f);
            Cb[(size_t)m*ldc + n] = v;
        }
    }
}

__global__ void conv_silu_k(const float* __restrict__ xz, const float* __restrict__ cw,
                            const float* __restrict__ cb, float* __restrict__ xc)
{
    int idx = blockIdx.x*256 + threadIdx.x;
    if (idx >= BL*DI) return;
    int d = idx & 127, bl = idx >> 7, l = bl & (LL-1);
    size_t base = (size_t)bl*256 + d;
    float acc = cb[d];
#pragma unroll
    for (int k=0;k<4;k++) {
        int lsrc = l - 3 + k;
        float v = (lsrc >= 0) ? xz[base + (size_t)(k-3)*256] : 0.f;
        acc = fmaf(cw[d*4+k], v, acc);
    }
    float sig = 1.f/(1.f+__expf(-acc));
    xc[idx] = acc*sig;
}

__global__ void dt_proj_k(const float* __restrict__ dbc, const float* __restrict__ Wdt,
                          const float* __restrict__ bdt, float* __restrict__ dt)
{
    int idx = blockIdx.x*256 + threadIdx.x;
    if (idx >= BL*DI) return;
    int d = idx & 127, bl = idx >> 7;
    const float* row = dbc + (size_t)bl*36;
    float s = bdt[d];
#pragma unroll
    for (int r=0;r<4;r++) s = fmaf(row[r], Wdt[r*128+d], s);
    dt[idx] = (s > 20.f) ? s : log1pf(__expf(s));
}

__global__ void scan1_k(const float* __restrict__ dt, const float* __restrict__ xc,
                        const float* __restrict__ dbc, const float* __restrict__ A_log,
                        float* __restrict__ hloc, float* __restrict__ cdout)
{
    int warp = threadIdx.x >> 5;
    int wg   = (blockIdx.x<<3) + warp;
    int lane = threadIdx.x & 31;
    int s = lane & 15, half = lane >> 4;
    int dpair = wg & 63, chunk = (wg>>6) & 63, b = wg>>12;
    int d = (dpair<<1) + half;
    float Aval = -__expf(A_log[d*16+s]);
    float h = 0.f, cd = 0.f;
    size_t rowbase = (size_t)b*LL + (chunk<<8);
    const float* dtp = dt  + rowbase*128 + d;
    const float* xcp = xc  + rowbase*128 + d;
    const float* bp  = dbc + rowbase*36 + 4 + s;
#pragma unroll 8
    for (int t=0;t<CHKS;t++) {
        float dtv = dtp[t*128], xcv = xcp[t*128], Bv = bp[t*36];
        h = fmaf(h, __expf(dtv*Aval), dtv*xcv*Bv);
        cd += dtv;
    }
    int cidx = (b*128+d)*NCHK + chunk;
    hloc[cidx*16+s] = h;
    if (s == 0 ) cdout[cidx] = cd;
}

__global__ void carry_k(const float* __restrict__ hloc, const float* __restrict__ cd,
                        const float* __restrict__ A_log, float* __restrict__ Hst)
{
    int idx = blockIdx.x*256 + threadIdx.x;
    if (idx >= BB*DI*DS) return;
    int s = idx & 15, d = (idx>>4)&127, b = idx>>11;
    float Aval = -__expf(A_log[d*16+s]);
    float H = 0.f;
    int base = (b*128+d)*NCHK;
    for (int c=0;c<NCHK;c++) {
        Hst[(base+c)*16+s] = H;
        H = fmaf(H, __expf(Aval*cd[base+c]), hloc[(base+c)*16+s]);
    }
}

__global__ void scan2_k(const float* __restrict__ dt, const float* __restrict__ xc,
                        const float* __restrict__ dbc, const float* __restrict__ A_log,
                        const float* __restrict__ Hst, const float* __restrict__ xz,
                        const float* __restrict__ Dvec, float* __restrict__ ygt)
{
    __shared__ float shy[8][2][CHKS];
    int warp = threadIdx.x >> 5;
    int wg   = (blockIdx.x<<3) + warp;
    int lane = threadIdx.x & 31;
    int s = lane & 15, half = lane >> 4;
    int dpair = wg & 63, chunk = (wg>>6) & 63, b = wg>>12;
    int d = (dpair<<1) + half;
    float Aval = -__expf(A_log[d*16+s]);
    float h = Hst[((b*128+d)*NCHK + chunk)*16 + s];
    float Dv = Dvec[d];
    int t0 = chunk<<8;
    size_t rowbase = (size_t)b*LL + t0;
    const float* dtp = dt  + rowbase*128 + d;
    const float* xcp = xc  + rowbase*128 + d;
    const float* bp  = dbc + rowbase*36 + 4 + s;
    const float* cp  = dbc + rowbase*36 + 20 + s;
    const float* zp  = xz  + rowbase*256 + 128 + d;
#pragma unroll 4
    for (int t=0;t<CHKS;t++) {
        float dtv = dtp[t*128], xcv = xcp[t*128], Bv = bp[t*36], Cv = cp[t*36];
        h = fmaf(h, __expf(dtv*Aval), dtv*xcv*Bv);
        float p = h*Cv;
        p += __shfl_xor_sync(0xffffffffu, p, 1);
        p += __shfl_xor_sync(0xffffffffu, p, 2);
        p += __shfl_xor_sync(0xffffffffu, p, 4);
        p += __shfl_xor_sync(0xffffffffu, p, 8);
        if (s == 0) {
            float zv = zp[(size_t)t*256];
            float y = fmaf(xcv, Dv, p);
            float sig = 1.f/(1.f+__expf(-zv));
            shy[warp][half][t] = y*zv*sig;
        }
    }
    __syncwarp();
#pragma unroll
    for (int r=0;r<2;r++) {
        int dd = (dpair<<1) + r;
        float* dst = ygt + ((size_t)b*128 + dd)*LL + t0;
        for (int t=lane;t<CHKS;t+=32) dst[t] = shy[warp][r][t];
    }
}

__global__ void mag_k(const float* __restrict__ re, const float* __restrict__ im,
                      float* __restrict__ mg)
{
    int i = blockIdx.x*256 + threadIdx.x;
    if (i >= NIMG*FPIX) return;
    float r = re[i], m = im[i];
    mg[i] = sqrtf(r*r + m*m);
}

__global__ void phase_k(const float* __restrict__ re, const float* __restrict__ im,
                        const float* __restrict__ mg, const float* __restrict__ M2,
                        float* __restrict__ Zr, float* __restrict__ Zi)
{
    int i = blockIdx.x*256 + threadIdx.x;
    if (i >= NIMG*FPIX) return;
    float m = mg[i], m2 = M2[i];
    if (m > 1e-20f) {
        float sc = m2/m;
        Zr[i] = re[i]*sc; Zi[i] = im[i]*sc;
    } else { Zr[i] = m2; Zi[i] = 0.f; }
}

__global__ void add_k(float* __restrict__ dst, const float* __restrict__ src)
{
    int i = blockIdx.x*256 + threadIdx.x;
    if (i < BB*CC*LL) dst[i] += src[i];
}

static void G(const float* A, const float* A2, int lam, int lak, int sA,
              const float* B, const float* B2, int lbk, int lbn, int sB,
              float* C, int ldc, int sC, int M, int N, int K, int batch,
              const float* bias, int bm, int relu)
{
    dim3 grid((N+63)>>6, (M+63)>>6, batch);
    if (A2) sgemm<true ><<<grid,256>>>(A,A2,lam,lak,sA,B,B2,lbk,lbn,sB,C,ldc,sC,M,N,K,bias,bm,relu);
    else    sgemm<false><<<grid,256>>>(A,nullptr,lam,lak,sA,B,nullptr,lbk,lbn,sB,C,ldc,sC,M,N,K,bias,bm,relu);
}

extern "C" void kernel_launch(void* const* d_in, const int* in_sizes, int n_in,
                              void* d_out, int out_size)
{
    const float* x      = (const float*)d_in[0];
    const float* W_in   = (const float*)d_in[1];
    const float* conv_w = (const float*)d_in[2];
    const float* conv_b = (const float*)d_in[3];
    const float* W_xproj= (const float*)d_in[4];
    const float* W_dt   = (const float*)d_in[5];
    const float* b_dt   = (const float*)d_in[6];
    const float* A_log  = (const float*)d_in[7];
    const float* Dvec   = (const float*)d_in[8];
    const float* W_out  = (const float*)d_in[9];
    const float* Wf1    = (const float*)d_in[10];
    const float* bf1    = (const float*)d_in[11];
    const float* Wf2    = (const float*)d_in[12];
    const float* bf2    = (const float*)d_in[13];
    const float* W_enh  = (const float*)d_in[14];
    const float* b_enh  = (const float*)d_in[15];
    const float* W_seg  = (const float*)d_in[16];
    const float* b_seg  = (const float*)d_in[17];
    float* out = (float*)d_out;

    void* pv;
    cudaGetSymbolAddress(&pv, d_xz);   float* p_xz  = (float*)pv;
    cudaGetSymbolAddress(&pv, d_xc);   float* p_xc  = (float*)pv;
    cudaGetSymbolAddress(&pv, d_dbc);  float* p_dbc = (float*)pv;
    cudaGetSymbolAddress(&pv, d_dt);   float* p_dt  = (float*)pv;
    cudaGetSymbolAddress(&pv, d_hloc); float* p_hl  = (float*)pv;
    cudaGetSymbolAddress(&pv, d_cd);   float* p_cd  = (float*)pv;
    cudaGetSymbolAddress(&pv, d_Hst);  float* p_Hs  = (float*)pv;
    cudaGetSymbolAddress(&pv, d_ygt);  float* p_yg  = (float*)pv;
    cudaGetSymbolAddress(&pv, d_xsp);  float* p_xsp = (float*)pv;
    cudaGetSymbolAddress(&pv, d_RT);   float* p_RT  = (float*)pv;
    cudaGetSymbolAddress(&pv, d_Cre);  float* p_Cre = (float*)pv;
    cudaGetSymbolAddress(&pv, d_Cim);  float* p_Cim = (float*)pv;
    cudaGetSymbolAddress(&pv, d_mag);  float* p_mag = (float*)pv;
    cudaGetSymbolAddress(&pv, d_M1);   float* p_M1  = (float*)pv;
    cudaGetSymbolAddress(&pv, d_M2);   float* p_M2  = (float*)pv;
    cudaGetSymbolAddress(&pv, d_Zr);   float* p_Zr  = (float*)pv;
    cudaGetSymbolAddress(&pv, d_Zi);   float* p_Zi  = (float*)pv;
    cudaGetSymbolAddress(&pv, d_Yr);   float* p_Yr  = (float*)pv;
    cudaGetSymbolAddress(&pv, d_Yi);   float* p_Yi  = (float*)pv;
    cudaGetSymbolAddress(&pv, d_xfr);  float* p_xfr = (float*)pv;
    cudaGetSymbolAddress(&pv, d_TW1);  float* p_TW1 = (float*)pv;
    cudaGetSymbolAddress(&pv, d_TCOS); float* p_TC  = (float*)pv;
    cudaGetSymbolAddress(&pv, d_TSIN); float* p_TS  = (float*)pv;
    cudaGetSymbolAddress(&pv, d_TSINN);float* p_TSN = (float*)pv;
    cudaGetSymbolAddress(&pv, d_IRW1); float* p_I1  = (float*)pv;
    cudaGetSymbolAddress(&pv, d_IRW2); float* p_I2  = (float*)pv;

    gen_tables<<<65, 256>>>();

    // ---- Mamba branch ----
    // xz[b] (L x 256) = xf[b] (L x 64) @ W_in ; xf[m,k] = x[b, k*L + m]
    G(x,0, 1, LL, CC*LL,  W_in,0, 256,1, 0,  p_xz, 256, LL*256,  LL, 256, CC, BB, 0,0,0);
    conv_silu_k<<<(BL*DI+255)/256,256>>>(p_xz, conv_w, conv_b, p_xc);
    // dbc (BL x 36) = xc (BL x 128) @ W_xproj
    G(p_xc,0, 128,1,0,  W_xproj,0, 36,1,0,  p_dbc, 36,0,  BL, 36, 128, 1, 0,0,0);
    dt_proj_k<<<(BL*DI+255)/256,256>>>(p_dbc, W_dt, b_dt, p_dt);
    scan1_k<<<2048,256>>>(p_dt, p_xc, p_dbc, A_log, p_hl, p_cd);
    carry_k<<<32,256>>>(p_hl, p_cd, A_log, p_Hs);
    scan2_k<<<2048,256>>>(p_dt, p_xc, p_dbc, A_log, p_Hs, p_xz, Dvec, p_yg);
    // x_spatial channel-major: xsp[b](64 x L) = W_out^T (64x128) @ ygt[b](128 x L)
    G(W_out,0, 1, CC, 0,  p_yg,0, LL,1, DI*LL,  p_xsp, LL, CC*LL,  CC, LL, DI, BB, 0,0,0);

    // ---- Frequency branch (DFT GEMMs) ----
    // row rfft: RT (32768 x 130) = x (32768 x 128) @ TW1
    G(x,0, 128,1,0,  p_TW1,0, 130,1,0,  p_RT, 130,0,  32768, 130, 128, 1, 0,0,0);
    // column FFT per image: Cre = TCOS@RTre + TSIN@RTim ; Cim = TCOS@RTim + TSINN@RTre
    G(p_TC, p_TS,  128,1,0,  p_RT, p_RT+65, 130,1, 128*130,  p_Cre, NKF, FPIX,  128, NKF, 128, NIMG, 0,0,0);
    G(p_TC, p_TSN, 128,1,0,  p_RT+65, p_RT, 130,1, 128*130,  p_Cim, NKF, FPIX,  128, NKF, 128, NIMG, 0,0,0);
    mag_k<<<(NIMG*FPIX+255)/256,256>>>(p_Cre, p_Cim, p_mag);
    // channel mix per batch: M1 = relu(Wf1 @ mag + bf1); M2 = Wf2 @ M1 + bf2
    G(Wf1,0, CC,1,0,  p_mag,0, FPIX,1, CC*FPIX,  p_M1, FPIX, CC*FPIX,  CC, FPIX, CC, BB, bf1, 2, 1);
    G(Wf2,0, CC,1,0,  p_M1,0,  FPIX,1, CC*FPIX,  p_M2, FPIX, CC*FPIX,  CC, FPIX, CC, BB, bf2, 2, 0);
    phase_k<<<(NIMG*FPIX+255)/256,256>>>(p_Cre, p_Cim, p_mag, p_M2, p_Zr, p_Zi);
    // inverse column FFT: Yr = TCOS@Zr + TSINN@Zi ; Yi = TSIN@Zr + TCOS@Zi
    G(p_TC, p_TSN, 128,1,0,  p_Zr, p_Zi, NKF,1, FPIX,  p_Yr, NKF, FPIX,  128, NKF, 128, NIMG, 0,0,0);
    G(p_TS, p_TC,  128,1,0,  p_Zr, p_Zi, NKF,1, FPIX,  p_Yi, NKF, FPIX,  128, NKF, 128, NIMG, 0,0,0);
    // irfft rows: xfr = Yr@IRW1 + Yi@IRW2   (per image, M=128 h, N=128 w, K=65)
    G(p_Yr, p_Yi, NKF,1, FPIX,  p_I1, p_I2, 128,1, 0,  p_xfr, 128, LL,  128, 128, NKF, NIMG, 0,0,0);

    // ---- Fuse + heads ----
    add_k<<<(BB*CC*LL+255)/256,256>>>(p_xfr, p_xsp);
    G(W_enh,0, CC,1,0,  p_xfr,0, LL,1, CC*LL,  out,            LL, CC*LL,  CC, LL, CC, BB, b_enh, 2, 0);
    G(W_seg,0, CC,1,0,  p_xfr,0, LL,1, CC*LL,  out + BB*CC*LL, LL, CC*LL,  CC, LL, CC, BB, b_seg, 2, 0);
}